// round 14
// baseline (speedup 1.0000x reference)
#include <cuda_runtime.h>

// CutStripes: out[b, :, t, :] = x[perm[b], :, t, :] if t falls inside any of 4
// stripes [bgn[b,s], bgn[b,s]+distance[b,s]), else x[b, :, t, :].
// Shapes: B=128, C=1, T=2048, F=128, STRIPES=4.
//
// R14 = converged R4/R13 warp-level code (8 rows/warp, front-batched LDG.128,
// one ballot per group, st.cs stores, all-int indexing) with the last unswept
// parameter: 512-thread blocks (2048 CTAs instead of 4096). Identical per-warp
// SASS; halves CTA launch/retire events and coarsens per-CTA address footprint
// to 16 KB. Expected neutral to -0.5% (last probe before declaring the
// hardware ceiling: 268 MB / 38.1us = 7.03 TB/s = 88% of 8 TB/s spec).
//
// Sweep record R2-R13: MLP 1->8 +18% (only real win); cp.async, ld.cs,
// persistent grid, 256-bit accesses, 8KB page groups: neutral/regression.

#define T_DIM         2048
#define F4            32        // 128 floats / 4
#define STRIPES       4
#define ROWS_PER_WARP 8
#define BLOCK_THREADS 512
#define WARPS_PER_BLK (BLOCK_THREADS / 32)   // 16

__global__ __launch_bounds__(BLOCK_THREADS) void cutstripes_kernel(
    const float4* __restrict__ x,
    const int*    __restrict__ perm,
    const int*    __restrict__ bgn,
    const int*    __restrict__ dist,
    float4*       __restrict__ out)
{
    const int warp = (blockIdx.x * BLOCK_THREADS + threadIdx.x) >> 5;  // group id
    const int lane = threadIdx.x & 31;

    // Each group = 8 consecutive t rows of one batch b (256 groups per batch).
    const int b  = warp >> 8;
    const int t0 = (warp & 255) * ROWS_PER_WARP;

    // Lane l checks row k=l>>2, stripe s=l&3 -> one ballot covers all 8 rows.
    const int k = lane >> 2;
    const int s = lane & 3;
    const int lo = __ldg(&bgn[b * STRIPES + s]);
    const int hi = lo + __ldg(&dist[b * STRIPES + s]);
    const bool in_stripe = ((t0 + k) >= lo) && ((t0 + k) < hi);
    const unsigned m = __ballot_sync(0xFFFFFFFFu, in_stripe);
    const int pb = __ldg(&perm[b]);

    // 8 independent LDG.128, front-batched (int indexing: max idx < 2^23).
    float4 v[ROWS_PER_WARP];
    #pragma unroll
    for (int r = 0; r < ROWS_PER_WARP; r++) {
        const int src = ((m >> (4 * r)) & 0xF) ? pb : b;
        const int src_idx = ((src << 11) | (t0 + r)) * F4 + lane;
        v[r] = x[src_idx];
    }

    // Streaming stores: evict-first write stream (wall-time-best variant).
    const int dst_base = ((b << 11) | t0) * F4 + lane;
    #pragma unroll
    for (int r = 0; r < ROWS_PER_WARP; r++) {
        __stcs(&out[dst_base + r * F4], v[r]);
    }
}

extern "C" void kernel_launch(void* const* d_in, const int* in_sizes, int n_in,
                              void* d_out, int out_size)
{
    const float4* x    = (const float4*)d_in[0];   // (128,1,2048,128) fp32
    const int*    perm = (const int*)   d_in[1];   // (128,)
    const int*    bgn  = (const int*)   d_in[2];   // (128,4)
    const int*    dist = (const int*)   d_in[3];   // (128,4)
    float4*       out  = (float4*)d_out;

    const int groups = 128 * T_DIM / ROWS_PER_WARP;   // 32768
    const int blocks = groups / WARPS_PER_BLK;        // 2048 blocks of 512 thr

    cutstripes_kernel<<<blocks, BLOCK_THREADS>>>(x, perm, bgn, dist, out);
}

// round 15
// speedup vs baseline: 1.0091x; 1.0091x over previous
#include <cuda_runtime.h>

// CutStripes: out[b, :, t, :] = x[perm[b], :, t, :] if t falls inside any of 4
// stripes [bgn[b,s], bgn[b,s]+distance[b,s]), else x[b, :, t, :].
// Shapes: B=128, C=1, T=2048, F=128, STRIPES=4.
//
// FINAL — converged configuration, twice reproduced at 45.15-45.22us wall /
// 38.08us ncu (best of session). Complete sweep record R2-R14:
//   +18%  warp-level row batching, 8 front-batched LDG.128 per thread (R2)
//   ~0    cp.async smem staging (R3) — proved MLP non-binding beyond ~3
//   ~0    st.cs stores (R4, kept: wall-best variant) / ld.cs worse (R12)
//   -7%   persistent grid-stride launch (R5)
//   -16%  256-bit double4 accesses (R6) — L1 replay wavefronts
//   ~0    16-row / 8KB page-locality groups (R11)
//   -1%   512-thread blocks (R14)
// Ceiling: 268 MB mandatory traffic / 38.1us = 7.03 TB/s combined = ~88% of
// 8 TB/s spec — the mixed read/write HBM turnaround limit. SM-side resources
// all <45% utilized; traffic irreducible (dense output tensor).

#define T_DIM         2048
#define F4            32        // 128 floats / 4
#define STRIPES       4
#define ROWS_PER_WARP 8
#define WARPS_PER_BLK 8

__global__ __launch_bounds__(256) void cutstripes_kernel(
    const float4* __restrict__ x,
    const int*    __restrict__ perm,
    const int*    __restrict__ bgn,
    const int*    __restrict__ dist,
    float4*       __restrict__ out)
{
    const int warp = (blockIdx.x * blockDim.x + threadIdx.x) >> 5;  // group id
    const int lane = threadIdx.x & 31;

    // Each group = 8 consecutive t rows of one batch b (256 groups per batch).
    const int b  = warp >> 8;
    const int t0 = (warp & 255) * ROWS_PER_WARP;

    // Lane l checks row k=l>>2, stripe s=l&3 -> one ballot covers all 8 rows.
    const int k = lane >> 2;
    const int s = lane & 3;
    const int lo = __ldg(&bgn[b * STRIPES + s]);
    const int hi = lo + __ldg(&dist[b * STRIPES + s]);
    const bool in_stripe = ((t0 + k) >= lo) && ((t0 + k) < hi);
    const unsigned m = __ballot_sync(0xFFFFFFFFu, in_stripe);
    const int pb = __ldg(&perm[b]);

    // 8 independent LDG.128, front-batched (int indexing: max idx < 2^23).
    float4 v[ROWS_PER_WARP];
    #pragma unroll
    for (int r = 0; r < ROWS_PER_WARP; r++) {
        const int src = ((m >> (4 * r)) & 0xF) ? pb : b;
        const int src_idx = ((src << 11) | (t0 + r)) * F4 + lane;
        v[r] = x[src_idx];
    }

    // Streaming stores: evict-first write stream (wall-time-best variant).
    const int dst_base = ((b << 11) | t0) * F4 + lane;
    #pragma unroll
    for (int r = 0; r < ROWS_PER_WARP; r++) {
        __stcs(&out[dst_base + r * F4], v[r]);
    }
}

extern "C" void kernel_launch(void* const* d_in, const int* in_sizes, int n_in,
                              void* d_out, int out_size)
{
    const float4* x    = (const float4*)d_in[0];   // (128,1,2048,128) fp32
    const int*    perm = (const int*)   d_in[1];   // (128,)
    const int*    bgn  = (const int*)   d_in[2];   // (128,4)
    const int*    dist = (const int*)   d_in[3];   // (128,4)
    float4*       out  = (float4*)d_out;

    const int groups = 128 * T_DIM / ROWS_PER_WARP;   // 32768
    const int blocks = groups / WARPS_PER_BLK;        // 4096

    cutstripes_kernel<<<blocks, 256>>>(x, perm, bgn, dist, out);
}

// round 16
// speedup vs baseline: 1.0105x; 1.0014x over previous
#include <cuda_runtime.h>

// CutStripes: out[b, :, t, :] = x[perm[b], :, t, :] if t falls inside any of 4
// stripes [bgn[b,s], bgn[b,s]+distance[b,s]), else x[b, :, t, :].
// Shapes: B=128, C=1, T=2048, F=128, STRIPES=4.
//
// R16: last unswept launch point — 128-thread blocks (8192 CTAs, 4 warps/CTA).
// Identical per-warp code to the thrice-reproduced best (38.1-38.2us ncu /
// 45.2-45.8us wall at block=256). Finer CTA granularity quantizes the final
// wave's tail more evenly across 148 SMs; bounded probe (block=512 cost -1%).
//
// Sweep record R2-R15: MLP 1->8 +18% (only win); cp.async, ld.cs, persistent
// grid, 256-bit accesses, 8KB page groups, 512-thr blocks: neutral/regression.
// Ceiling: 268 MB / 38.1us = 7.03 TB/s combined = ~88% of 8 TB/s spec.

#define T_DIM         2048
#define F4            32        // 128 floats / 4
#define STRIPES       4
#define ROWS_PER_WARP 8
#define BLOCK_THREADS 128
#define WARPS_PER_BLK (BLOCK_THREADS / 32)   // 4

__global__ __launch_bounds__(BLOCK_THREADS) void cutstripes_kernel(
    const float4* __restrict__ x,
    const int*    __restrict__ perm,
    const int*    __restrict__ bgn,
    const int*    __restrict__ dist,
    float4*       __restrict__ out)
{
    const int warp = (blockIdx.x * BLOCK_THREADS + threadIdx.x) >> 5;  // group id
    const int lane = threadIdx.x & 31;

    // Each group = 8 consecutive t rows of one batch b (256 groups per batch).
    const int b  = warp >> 8;
    const int t0 = (warp & 255) * ROWS_PER_WARP;

    // Lane l checks row k=l>>2, stripe s=l&3 -> one ballot covers all 8 rows.
    const int k = lane >> 2;
    const int s = lane & 3;
    const int lo = __ldg(&bgn[b * STRIPES + s]);
    const int hi = lo + __ldg(&dist[b * STRIPES + s]);
    const bool in_stripe = ((t0 + k) >= lo) && ((t0 + k) < hi);
    const unsigned m = __ballot_sync(0xFFFFFFFFu, in_stripe);
    const int pb = __ldg(&perm[b]);

    // 8 independent LDG.128, front-batched (int indexing: max idx < 2^23).
    float4 v[ROWS_PER_WARP];
    #pragma unroll
    for (int r = 0; r < ROWS_PER_WARP; r++) {
        const int src = ((m >> (4 * r)) & 0xF) ? pb : b;
        const int src_idx = ((src << 11) | (t0 + r)) * F4 + lane;
        v[r] = x[src_idx];
    }

    // Streaming stores: evict-first write stream (wall-time-best variant).
    const int dst_base = ((b << 11) | t0) * F4 + lane;
    #pragma unroll
    for (int r = 0; r < ROWS_PER_WARP; r++) {
        __stcs(&out[dst_base + r * F4], v[r]);
    }
}

extern "C" void kernel_launch(void* const* d_in, const int* in_sizes, int n_in,
                              void* d_out, int out_size)
{
    const float4* x    = (const float4*)d_in[0];   // (128,1,2048,128) fp32
    const int*    perm = (const int*)   d_in[1];   // (128,)
    const int*    bgn  = (const int*)   d_in[2];   // (128,4)
    const int*    dist = (const int*)   d_in[3];   // (128,4)
    float4*       out  = (float4*)d_out;

    const int groups = 128 * T_DIM / ROWS_PER_WARP;   // 32768
    const int blocks = groups / WARPS_PER_BLK;        // 8192 blocks of 128 thr

    cutstripes_kernel<<<blocks, BLOCK_THREADS>>>(x, perm, bgn, dist, out);
}

// round 17
// speedup vs baseline: 1.0126x; 1.0021x over previous
#include <cuda_runtime.h>

// CutStripes: out[b, :, t, :] = x[perm[b], :, t, :] if t falls inside any of 4
// stripes [bgn[b,s], bgn[b,s]+distance[b,s]), else x[b, :, t, :].
// Shapes: B=128, C=1, T=2048, F=128, STRIPES=4.
//
// FINAL — converged optimum, measured wall-best 45.15us / ncu-best 38.08us.
// Complete sweep record (R2-R16):
//   +18%  warp-level row batching: 8 front-batched LDG.128/thread (R2)
//   ~0    cp.async smem staging (R3) — MLP non-binding beyond ~3
//   ~0    st.cs stores (R4, kept: wall-best) / ld.cs worse (R12)
//   -7%   persistent grid-stride launch (R5)
//   -16%  256-bit double4 accesses (R6) — L1 replay wavefronts
//   ~0    16-row / 8KB page-locality groups (R11)
//   -1%   512-thread blocks (R14); ~0 128-thread blocks (R16)
// TMA store path pre-empted: LTS throughput is path-independent per B300
// microarch data (TMA == LDG.cv == ~6300 B/cyc).
// Ceiling: 268 MB mandatory traffic / 38.1us = 7.03 TB/s combined = ~88% of
// 8 TB/s spec — mixed read/write HBM turnaround limit. All SM counters <45%.

#define T_DIM         2048
#define F4            32        // 128 floats / 4
#define STRIPES       4
#define ROWS_PER_WARP 8
#define WARPS_PER_BLK 8

__global__ __launch_bounds__(256) void cutstripes_kernel(
    const float4* __restrict__ x,
    const int*    __restrict__ perm,
    const int*    __restrict__ bgn,
    const int*    __restrict__ dist,
    float4*       __restrict__ out)
{
    const int warp = (blockIdx.x * blockDim.x + threadIdx.x) >> 5;  // group id
    const int lane = threadIdx.x & 31;

    // Each group = 8 consecutive t rows of one batch b (256 groups per batch).
    const int b  = warp >> 8;
    const int t0 = (warp & 255) * ROWS_PER_WARP;

    // Lane l checks row k=l>>2, stripe s=l&3 -> one ballot covers all 8 rows.
    const int k = lane >> 2;
    const int s = lane & 3;
    const int lo = __ldg(&bgn[b * STRIPES + s]);
    const int hi = lo + __ldg(&dist[b * STRIPES + s]);
    const bool in_stripe = ((t0 + k) >= lo) && ((t0 + k) < hi);
    const unsigned m = __ballot_sync(0xFFFFFFFFu, in_stripe);
    const int pb = __ldg(&perm[b]);

    // 8 independent LDG.128, front-batched (int indexing: max idx < 2^23).
    float4 v[ROWS_PER_WARP];
    #pragma unroll
    for (int r = 0; r < ROWS_PER_WARP; r++) {
        const int src = ((m >> (4 * r)) & 0xF) ? pb : b;
        const int src_idx = ((src << 11) | (t0 + r)) * F4 + lane;
        v[r] = x[src_idx];
    }

    // Streaming stores: evict-first write stream (wall-time-best variant).
    const int dst_base = ((b << 11) | t0) * F4 + lane;
    #pragma unroll
    for (int r = 0; r < ROWS_PER_WARP; r++) {
        __stcs(&out[dst_base + r * F4], v[r]);
    }
}

extern "C" void kernel_launch(void* const* d_in, const int* in_sizes, int n_in,
                              void* d_out, int out_size)
{
    const float4* x    = (const float4*)d_in[0];   // (128,1,2048,128) fp32
    const int*    perm = (const int*)   d_in[1];   // (128,)
    const int*    bgn  = (const int*)   d_in[2];   // (128,4)
    const int*    dist = (const int*)   d_in[3];   // (128,4)
    float4*       out  = (float4*)d_out;

    const int groups = 128 * T_DIM / ROWS_PER_WARP;   // 32768
    const int blocks = groups / WARPS_PER_BLK;        // 4096

    cutstripes_kernel<<<blocks, 256>>>(x, perm, bgn, dist, out);
}